// round 1
// baseline (speedup 1.0000x reference)
#include <cuda_runtime.h>

#define NN 40000
#define NE 640000
#define NBATCH 64

// ---------------- scratch (device globals; no allocation allowed) ----------------
__device__ float g_xl[NN * 128];
__device__ float g_xr[NN * 128];
__device__ float g_h [NN * 128];
__device__ float g_logits[NE * 2];
__device__ int   g_rowptr[NN + 1];
__device__ int   g_cursor[NN];
__device__ int   g_eid[NE];
__device__ float g_gate[NN];
__device__ float g_gmax[NBATCH];
__device__ float g_gden[NBATCH];
__device__ float g_pooled[NBATCH * 64];

// ---------------- CSR build ----------------
__global__ void k_zero_cursor() {
    int i = blockIdx.x * blockDim.x + threadIdx.x;
    if (i < NN) g_cursor[i] = 0;
}
__global__ void k_count(const int* __restrict__ dst) {
    int e = blockIdx.x * blockDim.x + threadIdx.x;
    if (e < NE) atomicAdd(&g_cursor[dst[e]], 1);
}
// single-block inclusive scan over 40000 degrees -> rowptr
__global__ void k_scan() {
    __shared__ int s[2][1024];
    __shared__ int base_s;
    int tid = threadIdx.x;
    if (tid == 0) { base_s = 0; g_rowptr[0] = 0; }
    __syncthreads();
    for (int chunk = 0; chunk * 1024 < NN; chunk++) {
        int i = chunk * 1024 + tid;
        int v = (i < NN) ? g_cursor[i] : 0;
        int buf = 0;
        s[0][tid] = v;
        __syncthreads();
        #pragma unroll
        for (int off = 1; off < 1024; off <<= 1) {
            int t = s[buf][tid];
            if (tid >= off) t += s[buf][tid - off];
            s[1 - buf][tid] = t;
            buf ^= 1;
            __syncthreads();
        }
        int incl = s[buf][tid];
        int b = base_s;
        if (i < NN) g_rowptr[i + 1] = b + incl;
        __syncthreads();
        if (tid == 1023) base_s = b + incl;
        __syncthreads();
    }
}
__global__ void k_setcur() {
    int i = blockIdx.x * blockDim.x + threadIdx.x;
    if (i < NN) g_cursor[i] = g_rowptr[i];
}
__global__ void k_scatter(const int* __restrict__ dst) {
    int e = blockIdx.x * blockDim.x + threadIdx.x;
    if (e < NE) {
        int p = atomicAdd(&g_cursor[dst[e]], 1);
        g_eid[p] = e;
    }
}

// ---------------- tiled fp32 GEMM: C[M,N] = A[M,K] @ B[K,N] + bias (opt relu) ----
// BM=BN=64, BK=16, 256 threads, 4x4 microtile. Requires M%64==0, N%64==0, K%16==0.
__global__ void sgemm_bias(const float* __restrict__ A, const float* __restrict__ B,
                           const float* __restrict__ bias, float* __restrict__ C,
                           int M, int N, int K, int doRelu)
{
    __shared__ float sA[16][68];
    __shared__ float sB[16][68];
    int tid = threadIdx.x;
    int tx = tid & 15, ty = tid >> 4;
    int bm = blockIdx.y * 64, bn = blockIdx.x * 64;
    float acc[4][4];
    #pragma unroll
    for (int i = 0; i < 4; i++)
        #pragma unroll
        for (int j = 0; j < 4; j++) acc[i][j] = 0.f;

    int lm = tid >> 2, lk = (tid & 3) * 4;
    int kr = tid >> 4, nb = (tid & 15) * 4;
    for (int k0 = 0; k0 < K; k0 += 16) {
        float4 av = *(const float4*)&A[(size_t)(bm + lm) * K + k0 + lk];
        sA[lk + 0][lm] = av.x; sA[lk + 1][lm] = av.y;
        sA[lk + 2][lm] = av.z; sA[lk + 3][lm] = av.w;
        float4 bv = *(const float4*)&B[(size_t)(k0 + kr) * N + bn + nb];
        *(float4*)&sB[kr][nb] = bv;
        __syncthreads();
        #pragma unroll
        for (int k = 0; k < 16; k++) {
            float4 a = *(float4*)&sA[k][ty * 4];
            float4 b = *(float4*)&sB[k][tx * 4];
            float ar[4] = {a.x, a.y, a.z, a.w};
            float br[4] = {b.x, b.y, b.z, b.w};
            #pragma unroll
            for (int i = 0; i < 4; i++)
                #pragma unroll
                for (int j = 0; j < 4; j++) acc[i][j] += ar[i] * br[j];
        }
        __syncthreads();
    }
    float bs[4];
    #pragma unroll
    for (int j = 0; j < 4; j++) bs[j] = bias[bn + tx * 4 + j];
    #pragma unroll
    for (int i = 0; i < 4; i++) {
        float4 v;
        v.x = acc[i][0] + bs[0];
        v.y = acc[i][1] + bs[1];
        v.z = acc[i][2] + bs[2];
        v.w = acc[i][3] + bs[3];
        if (doRelu) {
            v.x = fmaxf(v.x, 0.f); v.y = fmaxf(v.y, 0.f);
            v.z = fmaxf(v.z, 0.f); v.w = fmaxf(v.w, 0.f);
        }
        *(float4*)&C[(size_t)(bm + ty * 4 + i) * N + bn + tx * 4] = v;
    }
}

// ---------------- edge logits: logits[e,h] = sum_c att[h,c]*lrelu(xl[src]+xr[dst]+ea@We) ----
// block = HC threads (thread = channel, owns We[:,c] in regs), 32 edges per block.
template<int HC, int H>
__global__ void edge_logits(const float* __restrict__ xl, const float* __restrict__ xr,
                            const float* __restrict__ We, const float* __restrict__ att,
                            const float* __restrict__ ea, const int* __restrict__ src,
                            const int* __restrict__ dst, float* __restrict__ logits)
{
    const int c = threadIdx.x;
    float wreg[32];
    #pragma unroll
    for (int k = 0; k < 32; k++) wreg[k] = We[k * HC + c];
    const float attv = att[c];
    __shared__ float s_ea[32][32];
    __shared__ int s_src[32], s_dst[32];
    __shared__ float s_logit[32 * H];
    const int lane = c & 31;
    const int hh = c / (HC / H);
    const long base = (long)blockIdx.x * 32;

    for (int i = c; i < 1024; i += HC)
        s_ea[i >> 5][i & 31] = ea[base * 32 + i];
    if (c < 32) { s_src[c] = src[base + c]; s_dst[c] = dst[base + c]; }
    if (c < 32 * H) s_logit[c] = 0.f;
    __syncthreads();

    #pragma unroll 2
    for (int j = 0; j < 32; j++) {
        float ee = 0.f;
        const float4* eav = (const float4*)s_ea[j];
        #pragma unroll
        for (int k4 = 0; k4 < 8; k4++) {
            float4 v = eav[k4];
            ee += v.x * wreg[k4 * 4 + 0] + v.y * wreg[k4 * 4 + 1]
                + v.z * wreg[k4 * 4 + 2] + v.w * wreg[k4 * 4 + 3];
        }
        float s = xl[(size_t)s_src[j] * HC + c] + xr[(size_t)s_dst[j] * HC + c] + ee;
        s = (s > 0.f) ? s : 0.2f * s;
        float p = s * attv;
        #pragma unroll
        for (int off = 16; off; off >>= 1) p += __shfl_down_sync(0xffffffffu, p, off);
        if (lane == 0) atomicAdd(&s_logit[j * H + hh], p);
    }
    __syncthreads();
    if (c < 32 * H) logits[base * H + c] = s_logit[c];
}

// ---------------- per-dst softmax + weighted aggregation of xl[src] ----------------
template<int HC, int H, bool RELU>
__global__ void agg(const float* __restrict__ xl, const float* __restrict__ logits,
                    const int* __restrict__ src, const float* __restrict__ bias,
                    float* __restrict__ out)
{
    const int n = blockIdx.x, c = threadIdx.x;
    const int wid = c >> 5, lane = c & 31;
    const int hh = c / (HC / H);
    __shared__ float s_max[H], s_den[H];
    __shared__ float s_w[H][64];
    __shared__ int s_srcn[64];
    const int r0 = g_rowptr[n], r1 = g_rowptr[n + 1], deg = r1 - r0;

    if (wid < H) {
        float m = -1e30f;
        for (int i = lane; i < deg; i += 32)
            m = fmaxf(m, logits[(size_t)g_eid[r0 + i] * H + wid]);
        #pragma unroll
        for (int off = 16; off; off >>= 1)
            m = fmaxf(m, __shfl_xor_sync(0xffffffffu, m, off));
        if (lane == 0) s_max[wid] = m;
    }
    __syncthreads();

    float acc = 0.f, dpart = 0.f;
    for (int b0 = 0; b0 < deg; b0 += 64) {
        int cnt = min(64, deg - b0);
        if (wid < H) {
            for (int i = lane; i < cnt; i += 32) {
                int e = g_eid[r0 + b0 + i];
                float w = __expf(logits[(size_t)e * H + wid] - s_max[wid]);
                s_w[wid][i] = w;
                dpart += w;
                if (wid == 0) s_srcn[i] = src[e];
            }
        }
        __syncthreads();
        for (int i = 0; i < cnt; i++)
            acc += s_w[hh][i] * xl[(size_t)s_srcn[i] * HC + c];
        __syncthreads();
    }
    if (wid < H) {
        #pragma unroll
        for (int off = 16; off; off >>= 1)
            dpart += __shfl_xor_sync(0xffffffffu, dpart, off);
        if (lane == 0) s_den[wid] = dpart;
    }
    __syncthreads();
    float res = acc / (s_den[hh] + 1e-16f) + bias[c];
    if (RELU) res = fmaxf(res, 0.f);
    out[(size_t)n * HC + c] = res;
}

// ---------------- pooling / head ----------------
__global__ void k_gate2(const float* __restrict__ hid, const float* __restrict__ G2w,
                        const float* __restrict__ G2b)
{
    int wid = threadIdx.x >> 5, lane = threadIdx.x & 31;
    int n = blockIdx.x * 4 + wid;
    if (n >= NN) return;
    float v = 0.f;
    #pragma unroll
    for (int i = 0; i < 4; i++) {
        int c = lane + 32 * i;
        v += hid[(size_t)n * 128 + c] * G2w[c];
    }
    #pragma unroll
    for (int off = 16; off; off >>= 1) v += __shfl_xor_sync(0xffffffffu, v, off);
    if (lane == 0) g_gate[n] = v + G2b[0];
}
__global__ void k_pool_init() {
    int i = blockIdx.x * blockDim.x + threadIdx.x;
    if (i < NBATCH * 64) g_pooled[i] = 0.f;
    if (i < NBATCH) { g_gmax[i] = -1e30f; g_gden[i] = 0.f; }
}
__device__ __forceinline__ void atomicMaxF(float* a, float v) {
    int* ai = (int*)a;
    int old = *ai;
    while (__int_as_float(old) < v) {
        int assumed = old;
        old = atomicCAS(ai, assumed, __float_as_int(v));
        if (old == assumed) break;
    }
}
__global__ void k_gmax(const int* __restrict__ batch) {
    int n = blockIdx.x * blockDim.x + threadIdx.x;
    if (n < NN) atomicMaxF(&g_gmax[batch[n]], g_gate[n]);
}
__global__ void k_gexp(const int* __restrict__ batch) {
    int n = blockIdx.x * blockDim.x + threadIdx.x;
    if (n < NN) {
        float w = __expf(g_gate[n] - g_gmax[batch[n]]);
        g_gate[n] = w;
        atomicAdd(&g_gden[batch[n]], w);
    }
}
__global__ void k_pool(const int* __restrict__ batch, const float* __restrict__ h3) {
    int idx = blockIdx.x * blockDim.x + threadIdx.x;
    if (idx < NN * 64) {
        int n = idx >> 6, cc = idx & 63;
        atomicAdd(&g_pooled[batch[n] * 64 + cc], g_gate[n] * h3[(size_t)n * 64 + cc]);
    }
}
__global__ void k_out(const float* __restrict__ Wreg, const float* __restrict__ breg,
                      float* __restrict__ out)
{
    int b = blockIdx.x, c = threadIdx.x;
    float v = g_pooled[b * 64 + c] * Wreg[c];
    #pragma unroll
    for (int off = 16; off; off >>= 1) v += __shfl_xor_sync(0xffffffffu, v, off);
    __shared__ float sp[2];
    if ((c & 31) == 0) sp[c >> 5] = v;
    __syncthreads();
    if (c == 0) out[b] = (sp[0] + sp[1]) / (g_gden[b] + 1e-16f) + breg[0];
}

// ---------------- launch ----------------
extern "C" void kernel_launch(void* const* d_in, const int* in_sizes, int n_in,
                              void* d_out, int out_size)
{
    const float* x     = (const float*)d_in[0];
    const float* eattr = (const float*)d_in[1];
    const int*   eidx  = (const int*)d_in[2];
    const int*   batch = (const int*)d_in[3];
    const float *W1l = (const float*)d_in[4],  *b1l = (const float*)d_in[5];
    const float *W1r = (const float*)d_in[6],  *b1r = (const float*)d_in[7];
    const float *W1e = (const float*)d_in[8],  *att1 = (const float*)d_in[9];
    const float *bias1 = (const float*)d_in[10];
    const float *W2l = (const float*)d_in[11], *b2l = (const float*)d_in[12];
    const float *W2r = (const float*)d_in[13], *b2r = (const float*)d_in[14];
    const float *W2e = (const float*)d_in[15], *att2 = (const float*)d_in[16];
    const float *bias2 = (const float*)d_in[17];
    const float *W3l = (const float*)d_in[18], *b3l = (const float*)d_in[19];
    const float *W3r = (const float*)d_in[20], *b3r = (const float*)d_in[21];
    const float *W3e = (const float*)d_in[22], *att3 = (const float*)d_in[23];
    const float *bias3 = (const float*)d_in[24];
    const float *G1w = (const float*)d_in[25], *G1b = (const float*)d_in[26];
    const float *G2w = (const float*)d_in[27], *G2b = (const float*)d_in[28];
    const float *Wreg = (const float*)d_in[29], *breg = (const float*)d_in[30];
    float* out = (float*)d_out;

    const int* src = eidx;
    const int* dst = eidx + NE;

    float *xl, *xr, *hbuf, *lg;
    cudaGetSymbolAddress((void**)&xl, g_xl);
    cudaGetSymbolAddress((void**)&xr, g_xr);
    cudaGetSymbolAddress((void**)&hbuf, g_h);
    cudaGetSymbolAddress((void**)&lg, g_logits);

    // CSR by dst
    k_zero_cursor<<<(NN + 255) / 256, 256>>>();
    k_count<<<(NE + 255) / 256, 256>>>(dst);
    k_scan<<<1, 1024>>>();
    k_setcur<<<(NN + 255) / 256, 256>>>();
    k_scatter<<<(NE + 255) / 256, 256>>>(dst);

    dim3 g2(2, NN / 64), g1(1, NN / 64);

    // ---- layer 1: 128 -> 2x64 concat ----
    sgemm_bias<<<g2, 256>>>(x, W1l, b1l, xl, NN, 128, 128, 0);
    sgemm_bias<<<g2, 256>>>(x, W1r, b1r, xr, NN, 128, 128, 0);
    edge_logits<128, 2><<<NE / 32, 128>>>(xl, xr, W1e, att1, eattr, src, dst, lg);
    agg<128, 2, true><<<NN, 128>>>(xl, lg, src, bias1, hbuf);

    // ---- layer 2: 128 -> 2x64 concat ----
    sgemm_bias<<<g2, 256>>>(hbuf, W2l, b2l, xl, NN, 128, 128, 0);
    sgemm_bias<<<g2, 256>>>(hbuf, W2r, b2r, xr, NN, 128, 128, 0);
    edge_logits<128, 2><<<NE / 32, 128>>>(xl, xr, W2e, att2, eattr, src, dst, lg);
    agg<128, 2, true><<<NN, 128>>>(xl, lg, src, bias2, hbuf);

    // ---- layer 3: 128 -> 64, 1 head, no concat ----
    sgemm_bias<<<g1, 256>>>(hbuf, W3l, b3l, xl, NN, 64, 128, 0);
    sgemm_bias<<<g1, 256>>>(hbuf, W3r, b3r, xr, NN, 64, 128, 0);
    edge_logits<64, 1><<<NE / 32, 64>>>(xl, xr, W3e, att3, eattr, src, dst, lg);
    agg<64, 1, false><<<NN, 64>>>(xl, lg, src, bias3, hbuf);   // hbuf now [N,64]

    // ---- attentional pooling + regressor ----
    sgemm_bias<<<g2, 256>>>(hbuf, G1w, G1b, xl, NN, 128, 64, 1);  // relu(h@G1w+G1b) -> xl[N,128]
    k_gate2<<<NN / 4, 128>>>(xl, G2w, G2b);
    k_pool_init<<<17, 256>>>();
    k_gmax<<<(NN + 255) / 256, 256>>>(batch);
    k_gexp<<<(NN + 255) / 256, 256>>>(batch);
    k_pool<<<(NN * 64 + 255) / 256, 256>>>(batch, hbuf);
    k_out<<<NBATCH, 64>>>(Wreg, breg, out);
}

// round 2
// speedup vs baseline: 1.0601x; 1.0601x over previous
#include <cuda_runtime.h>

#define NN 40000
#define NE 640000
#define NBATCH 64

typedef unsigned long long ull;

// ---------------- f32x2 helpers ----------------
__device__ __forceinline__ ull pk2(float lo, float hi) {
    ull r; asm("mov.b64 %0, {%1,%2};" : "=l"(r) : "f"(lo), "f"(hi)); return r;
}
__device__ __forceinline__ void upk2(ull v, float& lo, float& hi) {
    asm("mov.b64 {%0,%1}, %2;" : "=f"(lo), "=f"(hi) : "l"(v));
}
__device__ __forceinline__ ull fma2(ull a, ull b, ull c) {
    ull d; asm("fma.rn.f32x2 %0, %1, %2, %3;" : "=l"(d) : "l"(a), "l"(b), "l"(c)); return d;
}
union f4u { float4 f; ull u[2]; };

// ---------------- scratch (device globals) ----------------
__device__ float g_xl[NN * 128];
__device__ float g_xr[NN * 128];
__device__ float g_h [NN * 128];
__device__ float g_logits[NE * 2];
__device__ int   g_rowptr[NN + 1];
__device__ int   g_cursor[NN];
__device__ int   g_eid[NE];
__device__ float g_gate[NN];
__device__ float g_gmax[NBATCH];
__device__ float g_gden[NBATCH];
__device__ float g_pooled[NBATCH * 64];

// ---------------- CSR build ----------------
__global__ void k_zero_cursor() {
    int i = blockIdx.x * blockDim.x + threadIdx.x;
    if (i < NN) g_cursor[i] = 0;
}
__global__ void k_count(const int* __restrict__ dst) {
    int e = blockIdx.x * blockDim.x + threadIdx.x;
    if (e < NE) atomicAdd(&g_cursor[dst[e]], 1);
}
__global__ void k_scan() {
    __shared__ int s[2][1024];
    __shared__ int base_s;
    int tid = threadIdx.x;
    if (tid == 0) { base_s = 0; g_rowptr[0] = 0; }
    __syncthreads();
    for (int chunk = 0; chunk * 1024 < NN; chunk++) {
        int i = chunk * 1024 + tid;
        int v = (i < NN) ? g_cursor[i] : 0;
        int buf = 0;
        s[0][tid] = v;
        __syncthreads();
        #pragma unroll
        for (int off = 1; off < 1024; off <<= 1) {
            int t = s[buf][tid];
            if (tid >= off) t += s[buf][tid - off];
            s[1 - buf][tid] = t;
            buf ^= 1;
            __syncthreads();
        }
        int incl = s[buf][tid];
        int b = base_s;
        if (i < NN) g_rowptr[i + 1] = b + incl;
        __syncthreads();
        if (tid == 1023) base_s = b + incl;
        __syncthreads();
    }
}
__global__ void k_setcur() {
    int i = blockIdx.x * blockDim.x + threadIdx.x;
    if (i < NN) g_cursor[i] = g_rowptr[i];
}
__global__ void k_scatter(const int* __restrict__ dst) {
    int e = blockIdx.x * blockDim.x + threadIdx.x;
    if (e < NE) {
        int p = atomicAdd(&g_cursor[dst[e]], 1);
        g_eid[p] = e;
    }
}

// ---------------- f32x2 GEMM: C[M,N] = A[M,K] @ B[K,N] + bias (opt relu) --------
// BM=BN=64, BK=16, 128 threads, microtile 4 rows x 8 cols (4 col-pairs).
// A staged in smem as duplicated pairs so the inner loop needs no packing.
__global__ void __launch_bounds__(128) sgemm2(
    const float* __restrict__ A, const float* __restrict__ B,
    const float* __restrict__ bias, float* __restrict__ C,
    int M, int N, int K, int doRelu)
{
    __shared__ float2 sA[16][64];   // sA[k][row] = (a,a)  8KB
    __shared__ float  sB[16][64];   // 4KB
    const int tid = threadIdx.x;
    const int bm = blockIdx.y * 64, bn = blockIdx.x * 64;
    const int tx = tid & 7, ty = tid >> 3;        // cols tx*8..+7, rows ty*4..+3
    const int ar = tid >> 1, ak = (tid & 1) * 8;  // A stage: row ar, k off ak
    const int br = tid >> 3, bc = (tid & 7) * 8;  // B stage: k row br, col bc

    ull acc[4][4];
    #pragma unroll
    for (int i = 0; i < 4; i++)
        #pragma unroll
        for (int j = 0; j < 4; j++) acc[i][j] = 0ull;

    for (int k0 = 0; k0 < K; k0 += 16) {
        float4 a0 = *(const float4*)&A[(size_t)(bm + ar) * K + k0 + ak];
        float4 a1 = *(const float4*)&A[(size_t)(bm + ar) * K + k0 + ak + 4];
        sA[ak + 0][ar] = make_float2(a0.x, a0.x);
        sA[ak + 1][ar] = make_float2(a0.y, a0.y);
        sA[ak + 2][ar] = make_float2(a0.z, a0.z);
        sA[ak + 3][ar] = make_float2(a0.w, a0.w);
        sA[ak + 4][ar] = make_float2(a1.x, a1.x);
        sA[ak + 5][ar] = make_float2(a1.y, a1.y);
        sA[ak + 6][ar] = make_float2(a1.z, a1.z);
        sA[ak + 7][ar] = make_float2(a1.w, a1.w);
        *(float4*)&sB[br][bc]     = *(const float4*)&B[(size_t)(k0 + br) * N + bn + bc];
        *(float4*)&sB[br][bc + 4] = *(const float4*)&B[(size_t)(k0 + br) * N + bn + bc + 4];
        __syncthreads();
        #pragma unroll
        for (int k = 0; k < 16; k++) {
            f4u a01 = *(f4u*)&sA[k][ty * 4];
            f4u a23 = *(f4u*)&sA[k][ty * 4 + 2];
            f4u b01 = *(f4u*)&sB[k][tx * 8];
            f4u b23 = *(f4u*)&sB[k][tx * 8 + 4];
            ull av[4] = {a01.u[0], a01.u[1], a23.u[0], a23.u[1]};
            ull bv[4] = {b01.u[0], b01.u[1], b23.u[0], b23.u[1]};
            #pragma unroll
            for (int i = 0; i < 4; i++)
                #pragma unroll
                for (int j = 0; j < 4; j++)
                    acc[i][j] = fma2(av[i], bv[j], acc[i][j]);
        }
        __syncthreads();
    }
    float bs[8];
    #pragma unroll
    for (int j = 0; j < 8; j++) bs[j] = bias[bn + tx * 8 + j];
    #pragma unroll
    for (int i = 0; i < 4; i++) {
        float o[8];
        #pragma unroll
        for (int j = 0; j < 4; j++) upk2(acc[i][j], o[2 * j], o[2 * j + 1]);
        #pragma unroll
        for (int j = 0; j < 8; j++) {
            o[j] += bs[j];
            if (doRelu) o[j] = fmaxf(o[j], 0.f);
        }
        float4 v0 = make_float4(o[0], o[1], o[2], o[3]);
        float4 v1 = make_float4(o[4], o[5], o[6], o[7]);
        size_t row = (size_t)(bm + ty * 4 + i);
        *(float4*)&C[row * N + bn + tx * 8]     = v0;
        *(float4*)&C[row * N + bn + tx * 8 + 4] = v1;
    }
}

// ---------------- edge logits (f32x2): thread = channel pair --------------------
// logits[e,h] = sum_c att[h,c] * lrelu(xl[src,c] + xr[dst,c] + (ea@We)[e,c])
// Block: HC/2 threads (H warps), 128 edges per block in 4 groups of 32.
template<int HC, int H>
__global__ void __launch_bounds__(HC / 2) edge_logits2(
    const float* __restrict__ xl, const float* __restrict__ xr,
    const float* __restrict__ We, const float* __restrict__ att,
    const float* __restrict__ ea, const int* __restrict__ src,
    const int* __restrict__ dst, float* __restrict__ logits)
{
    const int t = threadIdx.x;           // channel pair index
    const int lane = t & 31, wid = t >> 5;   // wid == head
    ull w2[32];
    #pragma unroll
    for (int k = 0; k < 32; k++) {
        float2 w = *(const float2*)&We[k * HC + 2 * t];
        w2[k] = pk2(w.x, w.y);
    }
    const float attlo = att[2 * t], atthi = att[2 * t + 1];

    __shared__ float2 sea[32][32];       // duplicated pairs, 8KB
    __shared__ int ssrc[32], sdst[32];

    for (int grp = 0; grp < 4; grp++) {
        const long base = (long)blockIdx.x * 128 + grp * 32;
        const float4* p4 = (const float4*)(ea + base * 32);
        for (int i = t; i < 256; i += HC / 2) {
            float4 v = p4[i];
            float4* d = (float4*)&sea[i >> 3][(4 * i) & 31];
            d[0] = make_float4(v.x, v.x, v.y, v.y);
            d[1] = make_float4(v.z, v.z, v.w, v.w);
        }
        if (t < 32) { ssrc[t] = src[base + t]; sdst[t] = dst[base + t]; }
        __syncthreads();

        for (int j = 0; j < 32; j++) {
            ull ee = 0ull;
            const f4u* ev = (const f4u*)sea[j];
            #pragma unroll
            for (int kk = 0; kk < 16; kk++) {
                f4u v = ev[kk];
                ee = fma2(v.u[0], w2[2 * kk], ee);
                ee = fma2(v.u[1], w2[2 * kk + 1], ee);
            }
            float eelo, eehi; upk2(ee, eelo, eehi);
            float2 xlv = *(const float2*)&xl[(size_t)ssrc[j] * HC + 2 * t];
            float2 xrv = *(const float2*)&xr[(size_t)sdst[j] * HC + 2 * t];
            float slo = xlv.x + xrv.x + eelo;
            float shi = xlv.y + xrv.y + eehi;
            slo = fmaxf(slo, 0.f) + 0.2f * fminf(slo, 0.f);
            shi = fmaxf(shi, 0.f) + 0.2f * fminf(shi, 0.f);
            float p = slo * attlo + shi * atthi;
            #pragma unroll
            for (int off = 16; off; off >>= 1)
                p += __shfl_down_sync(0xffffffffu, p, off);
            if (lane == 0) logits[(base + j) * H + wid] = p;
        }
        __syncthreads();
    }
}

// ---------------- per-dst softmax + weighted aggregation (no max pass) ----------
template<int HC, int H, bool RELU>
__global__ void __launch_bounds__(HC / 2) agg2(
    const float* __restrict__ xl, const float* __restrict__ logits,
    const int* __restrict__ src, const float* __restrict__ bias,
    float* __restrict__ out)
{
    const int n = blockIdx.x, t = threadIdx.x;
    const int lane = t & 31, wid = t >> 5;   // wid == head
    __shared__ float s_w[H][64];
    __shared__ int s_srcn[64];
    __shared__ float s_den[H];
    const int r0 = g_rowptr[n], deg = g_rowptr[n + 1] - r0;

    float accx = 0.f, accy = 0.f, dpart = 0.f;
    for (int b0 = 0; b0 < deg; b0 += 64) {
        int cnt = min(64, deg - b0);
        for (int i = lane; i < cnt; i += 32) {
            int e = g_eid[r0 + b0 + i];
            float w = __expf(logits[(size_t)e * H + wid]);
            s_w[wid][i] = w;
            dpart += w;
            if (wid == 0) s_srcn[i] = src[e];
        }
        __syncthreads();
        for (int i = 0; i < cnt; i++) {
            float w = s_w[wid][i];
            float2 v = *(const float2*)&xl[(size_t)s_srcn[i] * HC + 2 * t];
            accx += w * v.x;
            accy += w * v.y;
        }
        __syncthreads();
    }
    #pragma unroll
    for (int off = 16; off; off >>= 1)
        dpart += __shfl_xor_sync(0xffffffffu, dpart, off);
    if (lane == 0) s_den[wid] = dpart;
    __syncthreads();
    float inv = 1.f / (s_den[wid] + 1e-16f);
    float ox = accx * inv + bias[2 * t];
    float oy = accy * inv + bias[2 * t + 1];
    if (RELU) { ox = fmaxf(ox, 0.f); oy = fmaxf(oy, 0.f); }
    *(float2*)&out[(size_t)n * HC + 2 * t] = make_float2(ox, oy);
}

// ---------------- pooling / head ----------------
__global__ void k_gate2(const float* __restrict__ hid, const float* __restrict__ G2w,
                        const float* __restrict__ G2b)
{
    int wid = threadIdx.x >> 5, lane = threadIdx.x & 31;
    int n = blockIdx.x * 4 + wid;
    if (n >= NN) return;
    float v = 0.f;
    #pragma unroll
    for (int i = 0; i < 4; i++) {
        int c = lane + 32 * i;
        v += hid[(size_t)n * 128 + c] * G2w[c];
    }
    #pragma unroll
    for (int off = 16; off; off >>= 1) v += __shfl_xor_sync(0xffffffffu, v, off);
    if (lane == 0) g_gate[n] = v + G2b[0];
}
__global__ void k_pool_init() {
    int i = blockIdx.x * blockDim.x + threadIdx.x;
    if (i < NBATCH * 64) g_pooled[i] = 0.f;
    if (i < NBATCH) { g_gmax[i] = -1e30f; g_gden[i] = 0.f; }
}
__device__ __forceinline__ void atomicMaxF(float* a, float v) {
    int* ai = (int*)a;
    int old = *ai;
    while (__int_as_float(old) < v) {
        int assumed = old;
        old = atomicCAS(ai, assumed, __float_as_int(v));
        if (old == assumed) break;
    }
}
__global__ void k_gmax(const int* __restrict__ batch) {
    int n = blockIdx.x * blockDim.x + threadIdx.x;
    if (n < NN) atomicMaxF(&g_gmax[batch[n]], g_gate[n]);
}
__global__ void k_gexp(const int* __restrict__ batch) {
    int n = blockIdx.x * blockDim.x + threadIdx.x;
    if (n < NN) {
        float w = __expf(g_gate[n] - g_gmax[batch[n]]);
        g_gate[n] = w;
        atomicAdd(&g_gden[batch[n]], w);
    }
}
__global__ void k_pool(const int* __restrict__ batch, const float* __restrict__ h3) {
    int idx = blockIdx.x * blockDim.x + threadIdx.x;
    if (idx < NN * 64) {
        int n = idx >> 6, cc = idx & 63;
        atomicAdd(&g_pooled[batch[n] * 64 + cc], g_gate[n] * h3[(size_t)n * 64 + cc]);
    }
}
__global__ void k_out(const float* __restrict__ Wreg, const float* __restrict__ breg,
                      float* __restrict__ out)
{
    int b = blockIdx.x, c = threadIdx.x;
    float v = g_pooled[b * 64 + c] * Wreg[c];
    #pragma unroll
    for (int off = 16; off; off >>= 1) v += __shfl_xor_sync(0xffffffffu, v, off);
    __shared__ float sp[2];
    if ((c & 31) == 0) sp[c >> 5] = v;
    __syncthreads();
    if (c == 0) out[b] = (sp[0] + sp[1]) / (g_gden[b] + 1e-16f) + breg[0];
}

// ---------------- launch ----------------
extern "C" void kernel_launch(void* const* d_in, const int* in_sizes, int n_in,
                              void* d_out, int out_size)
{
    const float* x     = (const float*)d_in[0];
    const float* eattr = (const float*)d_in[1];
    const int*   eidx  = (const int*)d_in[2];
    const int*   batch = (const int*)d_in[3];
    const float *W1l = (const float*)d_in[4],  *b1l = (const float*)d_in[5];
    const float *W1r = (const float*)d_in[6],  *b1r = (const float*)d_in[7];
    const float *W1e = (const float*)d_in[8],  *att1 = (const float*)d_in[9];
    const float *bias1 = (const float*)d_in[10];
    const float *W2l = (const float*)d_in[11], *b2l = (const float*)d_in[12];
    const float *W2r = (const float*)d_in[13], *b2r = (const float*)d_in[14];
    const float *W2e = (const float*)d_in[15], *att2 = (const float*)d_in[16];
    const float *bias2 = (const float*)d_in[17];
    const float *W3l = (const float*)d_in[18], *b3l = (const float*)d_in[19];
    const float *W3r = (const float*)d_in[20], *b3r = (const float*)d_in[21];
    const float *W3e = (const float*)d_in[22], *att3 = (const float*)d_in[23];
    const float *bias3 = (const float*)d_in[24];
    const float *G1w = (const float*)d_in[25], *G1b = (const float*)d_in[26];
    const float *G2w = (const float*)d_in[27], *G2b = (const float*)d_in[28];
    const float *Wreg = (const float*)d_in[29], *breg = (const float*)d_in[30];
    float* out = (float*)d_out;

    const int* src = eidx;
    const int* dst = eidx + NE;

    float *xl, *xr, *hbuf, *lg;
    cudaGetSymbolAddress((void**)&xl, g_xl);
    cudaGetSymbolAddress((void**)&xr, g_xr);
    cudaGetSymbolAddress((void**)&hbuf, g_h);
    cudaGetSymbolAddress((void**)&lg, g_logits);

    // CSR by dst
    k_zero_cursor<<<(NN + 255) / 256, 256>>>();
    k_count<<<(NE + 255) / 256, 256>>>(dst);
    k_scan<<<1, 1024>>>();
    k_setcur<<<(NN + 255) / 256, 256>>>();
    k_scatter<<<(NE + 255) / 256, 256>>>(dst);

    dim3 g2(2, NN / 64), g1(1, NN / 64);

    // ---- layer 1: 128 -> 2x64 concat ----
    sgemm2<<<g2, 128>>>(x, W1l, b1l, xl, NN, 128, 128, 0);
    sgemm2<<<g2, 128>>>(x, W1r, b1r, xr, NN, 128, 128, 0);
    edge_logits2<128, 2><<<NE / 128, 64>>>(xl, xr, W1e, att1, eattr, src, dst, lg);
    agg2<128, 2, true><<<NN, 64>>>(xl, lg, src, bias1, hbuf);

    // ---- layer 2: 128 -> 2x64 concat ----
    sgemm2<<<g2, 128>>>(hbuf, W2l, b2l, xl, NN, 128, 128, 0);
    sgemm2<<<g2, 128>>>(hbuf, W2r, b2r, xr, NN, 128, 128, 0);
    edge_logits2<128, 2><<<NE / 128, 64>>>(xl, xr, W2e, att2, eattr, src, dst, lg);
    agg2<128, 2, true><<<NN, 64>>>(xl, lg, src, bias2, hbuf);

    // ---- layer 3: 128 -> 64, 1 head, no concat ----
    sgemm2<<<g1, 128>>>(hbuf, W3l, b3l, xl, NN, 64, 128, 0);
    sgemm2<<<g1, 128>>>(hbuf, W3r, b3r, xr, NN, 64, 128, 0);
    edge_logits2<64, 1><<<NE / 128, 32>>>(xl, xr, W3e, att3, eattr, src, dst, lg);
    agg2<64, 1, false><<<NN, 32>>>(xl, lg, src, bias3, hbuf);   // hbuf now [N,64]

    // ---- attentional pooling + regressor ----
    sgemm2<<<g2, 128>>>(hbuf, G1w, G1b, xl, NN, 128, 64, 1);  // relu(h@G1w+G1b) -> xl[N,128]
    k_gate2<<<NN / 4, 128>>>(xl, G2w, G2b);
    k_pool_init<<<17, 256>>>();
    k_gmax<<<(NN + 255) / 256, 256>>>(batch);
    k_gexp<<<(NN + 255) / 256, 256>>>(batch);
    k_pool<<<(NN * 64 + 255) / 256, 256>>>(batch, hbuf);
    k_out<<<NBATCH, 64>>>(Wreg, breg, out);
}

// round 3
// speedup vs baseline: 1.1418x; 1.0771x over previous
#include <cuda_runtime.h>

#define NN 40000
#define NE 640000
#define NBATCH 64

typedef unsigned long long ull;

// ---------------- f32x2 helpers ----------------
__device__ __forceinline__ ull pk2(float lo, float hi) {
    ull r; asm("mov.b64 %0, {%1,%2};" : "=l"(r) : "f"(lo), "f"(hi)); return r;
}
__device__ __forceinline__ void upk2(ull v, float& lo, float& hi) {
    asm("mov.b64 {%0,%1}, %2;" : "=f"(lo), "=f"(hi) : "l"(v));
}
__device__ __forceinline__ ull fma2(ull a, ull b, ull c) {
    ull d; asm("fma.rn.f32x2 %0, %1, %2, %3;" : "=l"(d) : "l"(a), "l"(b), "l"(c)); return d;
}
union f4u { float4 f; ull u[2]; };

// ---------------- scratch ----------------
__device__ float g_xl[NN * 128];
__device__ float g_xr[NN * 128];
__device__ float g_h [NN * 128];
__device__ float g_w  [NE * 2];       // exp(logit)
__device__ int   g_rowptr[NN + 1];
__device__ int   g_cursor[NN];
__device__ int   g_eid[NE];
__device__ float g_gate[NN];          // exp(gate logit)

// ---------------- CSR build ----------------
__global__ void k_init() {
    int i = blockIdx.x * blockDim.x + threadIdx.x;
    if (i < NN) g_cursor[i] = 0;
}
__global__ void k_count(const int* __restrict__ dst) {
    int e = blockIdx.x * blockDim.x + threadIdx.x;
    if (e < NE) atomicAdd(&g_cursor[dst[e]], 1);
}
// single-block scan: writes rowptr AND resets cursor to row start
__global__ void k_scan() {
    __shared__ int s[2][1024];
    __shared__ int base_s;
    int tid = threadIdx.x;
    if (tid == 0) { base_s = 0; g_rowptr[0] = 0; }
    __syncthreads();
    for (int chunk = 0; chunk * 1024 < NN; chunk++) {
        int i = chunk * 1024 + tid;
        int v = (i < NN) ? g_cursor[i] : 0;
        int buf = 0;
        s[0][tid] = v;
        __syncthreads();
        #pragma unroll
        for (int off = 1; off < 1024; off <<= 1) {
            int t = s[buf][tid];
            if (tid >= off) t += s[buf][tid - off];
            s[1 - buf][tid] = t;
            buf ^= 1;
            __syncthreads();
        }
        int incl = s[buf][tid];
        int b = base_s;
        if (i < NN) {
            g_rowptr[i + 1] = b + incl;
            g_cursor[i] = b + incl - v;   // exclusive prefix = row start
        }
        __syncthreads();
        if (tid == 1023) base_s = b + incl;
        __syncthreads();
    }
}
__global__ void k_scatter(const int* __restrict__ dst) {
    int e = blockIdx.x * blockDim.x + threadIdx.x;
    if (e < NE) {
        int p = atomicAdd(&g_cursor[dst[e]], 1);
        g_eid[p] = e;
    }
}

// ---------------- dual f32x2 GEMM: Cl = A@Bl + bl, Cr = A@Br + br ----------------
// BM=BN=64, BK=16, 128 threads, microtile 4x8 per output.
__global__ void __launch_bounds__(128, 4) sgemm_dual(
    const float* __restrict__ A,
    const float* __restrict__ Bl, const float* __restrict__ bil, float* __restrict__ Cl,
    const float* __restrict__ Br, const float* __restrict__ bir, float* __restrict__ Cr,
    int M, int N, int K)
{
    __shared__ float2 sA[16][64];
    __shared__ float  sBl[16][64];
    __shared__ float  sBr[16][64];
    const int tid = threadIdx.x;
    const int bm = blockIdx.y * 64, bn = blockIdx.x * 64;
    const int tx = tid & 7, ty = tid >> 3;
    const int ar = tid >> 1, ak = (tid & 1) * 8;
    const int br = tid >> 3, bc = (tid & 7) * 8;

    ull accl[4][4], accr[4][4];
    #pragma unroll
    for (int i = 0; i < 4; i++)
        #pragma unroll
        for (int j = 0; j < 4; j++) { accl[i][j] = 0ull; accr[i][j] = 0ull; }

    for (int k0 = 0; k0 < K; k0 += 16) {
        float4 a0 = *(const float4*)&A[(size_t)(bm + ar) * K + k0 + ak];
        float4 a1 = *(const float4*)&A[(size_t)(bm + ar) * K + k0 + ak + 4];
        sA[ak + 0][ar] = make_float2(a0.x, a0.x);
        sA[ak + 1][ar] = make_float2(a0.y, a0.y);
        sA[ak + 2][ar] = make_float2(a0.z, a0.z);
        sA[ak + 3][ar] = make_float2(a0.w, a0.w);
        sA[ak + 4][ar] = make_float2(a1.x, a1.x);
        sA[ak + 5][ar] = make_float2(a1.y, a1.y);
        sA[ak + 6][ar] = make_float2(a1.z, a1.z);
        sA[ak + 7][ar] = make_float2(a1.w, a1.w);
        *(float4*)&sBl[br][bc]     = *(const float4*)&Bl[(size_t)(k0 + br) * N + bn + bc];
        *(float4*)&sBl[br][bc + 4] = *(const float4*)&Bl[(size_t)(k0 + br) * N + bn + bc + 4];
        *(float4*)&sBr[br][bc]     = *(const float4*)&Br[(size_t)(k0 + br) * N + bn + bc];
        *(float4*)&sBr[br][bc + 4] = *(const float4*)&Br[(size_t)(k0 + br) * N + bn + bc + 4];
        __syncthreads();
        #pragma unroll
        for (int k = 0; k < 16; k++) {
            f4u a01 = *(f4u*)&sA[k][ty * 4];
            f4u a23 = *(f4u*)&sA[k][ty * 4 + 2];
            f4u bl01 = *(f4u*)&sBl[k][tx * 8];
            f4u bl23 = *(f4u*)&sBl[k][tx * 8 + 4];
            f4u br01 = *(f4u*)&sBr[k][tx * 8];
            f4u br23 = *(f4u*)&sBr[k][tx * 8 + 4];
            ull av[4] = {a01.u[0], a01.u[1], a23.u[0], a23.u[1]};
            ull blv[4] = {bl01.u[0], bl01.u[1], bl23.u[0], bl23.u[1]};
            ull brv[4] = {br01.u[0], br01.u[1], br23.u[0], br23.u[1]};
            #pragma unroll
            for (int i = 0; i < 4; i++)
                #pragma unroll
                for (int j = 0; j < 4; j++) {
                    accl[i][j] = fma2(av[i], blv[j], accl[i][j]);
                    accr[i][j] = fma2(av[i], brv[j], accr[i][j]);
                }
        }
        __syncthreads();
    }
    float bsl[8], bsr[8];
    #pragma unroll
    for (int j = 0; j < 8; j++) { bsl[j] = bil[bn + tx * 8 + j]; bsr[j] = bir[bn + tx * 8 + j]; }
    #pragma unroll
    for (int i = 0; i < 4; i++) {
        float ol[8], orr[8];
        #pragma unroll
        for (int j = 0; j < 4; j++) {
            upk2(accl[i][j], ol[2 * j], ol[2 * j + 1]);
            upk2(accr[i][j], orr[2 * j], orr[2 * j + 1]);
        }
        #pragma unroll
        for (int j = 0; j < 8; j++) { ol[j] += bsl[j]; orr[j] += bsr[j]; }
        size_t row = (size_t)(bm + ty * 4 + i);
        *(float4*)&Cl[row * N + bn + tx * 8]     = make_float4(ol[0], ol[1], ol[2], ol[3]);
        *(float4*)&Cl[row * N + bn + tx * 8 + 4] = make_float4(ol[4], ol[5], ol[6], ol[7]);
        *(float4*)&Cr[row * N + bn + tx * 8]     = make_float4(orr[0], orr[1], orr[2], orr[3]);
        *(float4*)&Cr[row * N + bn + tx * 8 + 4] = make_float4(orr[4], orr[5], orr[6], orr[7]);
    }
}

// ---------------- single GEMM (for gate layer, with relu) ----------------
__global__ void __launch_bounds__(128) sgemm2(
    const float* __restrict__ A, const float* __restrict__ B,
    const float* __restrict__ bias, float* __restrict__ C,
    int M, int N, int K, int doRelu)
{
    __shared__ float2 sA[16][64];
    __shared__ float  sB[16][64];
    const int tid = threadIdx.x;
    const int bm = blockIdx.y * 64, bn = blockIdx.x * 64;
    const int tx = tid & 7, ty = tid >> 3;
    const int ar = tid >> 1, ak = (tid & 1) * 8;
    const int br = tid >> 3, bc = (tid & 7) * 8;

    ull acc[4][4];
    #pragma unroll
    for (int i = 0; i < 4; i++)
        #pragma unroll
        for (int j = 0; j < 4; j++) acc[i][j] = 0ull;

    for (int k0 = 0; k0 < K; k0 += 16) {
        float4 a0 = *(const float4*)&A[(size_t)(bm + ar) * K + k0 + ak];
        float4 a1 = *(const float4*)&A[(size_t)(bm + ar) * K + k0 + ak + 4];
        sA[ak + 0][ar] = make_float2(a0.x, a0.x);
        sA[ak + 1][ar] = make_float2(a0.y, a0.y);
        sA[ak + 2][ar] = make_float2(a0.z, a0.z);
        sA[ak + 3][ar] = make_float2(a0.w, a0.w);
        sA[ak + 4][ar] = make_float2(a1.x, a1.x);
        sA[ak + 5][ar] = make_float2(a1.y, a1.y);
        sA[ak + 6][ar] = make_float2(a1.z, a1.z);
        sA[ak + 7][ar] = make_float2(a1.w, a1.w);
        *(float4*)&sB[br][bc]     = *(const float4*)&B[(size_t)(k0 + br) * N + bn + bc];
        *(float4*)&sB[br][bc + 4] = *(const float4*)&B[(size_t)(k0 + br) * N + bn + bc + 4];
        __syncthreads();
        #pragma unroll
        for (int k = 0; k < 16; k++) {
            f4u a01 = *(f4u*)&sA[k][ty * 4];
            f4u a23 = *(f4u*)&sA[k][ty * 4 + 2];
            f4u b01 = *(f4u*)&sB[k][tx * 8];
            f4u b23 = *(f4u*)&sB[k][tx * 8 + 4];
            ull av[4] = {a01.u[0], a01.u[1], a23.u[0], a23.u[1]};
            ull bv[4] = {b01.u[0], b01.u[1], b23.u[0], b23.u[1]};
            #pragma unroll
            for (int i = 0; i < 4; i++)
                #pragma unroll
                for (int j = 0; j < 4; j++)
                    acc[i][j] = fma2(av[i], bv[j], acc[i][j]);
        }
        __syncthreads();
    }
    float bs[8];
    #pragma unroll
    for (int j = 0; j < 8; j++) bs[j] = bias[bn + tx * 8 + j];
    #pragma unroll
    for (int i = 0; i < 4; i++) {
        float o[8];
        #pragma unroll
        for (int j = 0; j < 4; j++) upk2(acc[i][j], o[2 * j], o[2 * j + 1]);
        #pragma unroll
        for (int j = 0; j < 8; j++) {
            o[j] += bs[j];
            if (doRelu) o[j] = fmaxf(o[j], 0.f);
        }
        size_t row = (size_t)(bm + ty * 4 + i);
        *(float4*)&C[row * N + bn + tx * 8]     = make_float4(o[0], o[1], o[2], o[3]);
        *(float4*)&C[row * N + bn + tx * 8 + 4] = make_float4(o[4], o[5], o[6], o[7]);
    }
}

// ---------------- edge weights: w[e,h] = exp(att_h . lrelu(xl[src]+xr[dst]+ea@We)) ----
// 2-edge unroll, dual ee accumulators, gathers hoisted.
template<int HC, int H>
__global__ void __launch_bounds__(HC / 2, 8) edge_logits3(
    const float* __restrict__ xl, const float* __restrict__ xr,
    const float* __restrict__ We, const float* __restrict__ att,
    const float* __restrict__ ea, const int* __restrict__ src,
    const int* __restrict__ dst, float* __restrict__ wout)
{
    const int t = threadIdx.x;
    const int lane = t & 31, wid = t >> 5;   // wid == head
    ull w2[32];
    #pragma unroll
    for (int k = 0; k < 32; k++) {
        float2 w = *(const float2*)&We[k * HC + 2 * t];
        w2[k] = pk2(w.x, w.y);
    }
    const float attlo = att[2 * t], atthi = att[2 * t + 1];
    const float2* xl2 = (const float2*)xl;
    const float2* xr2 = (const float2*)xr;
    const int HC2 = HC / 2;

    __shared__ float2 sea[32][32];
    __shared__ int ssrc[32], sdst[32];

    for (int grp = 0; grp < 4; grp++) {
        const long base = (long)blockIdx.x * 128 + grp * 32;
        const float4* p4 = (const float4*)(ea + base * 32);
        for (int i = t; i < 256; i += HC / 2) {
            float4 v = p4[i];
            float4* d = (float4*)&sea[i >> 3][(4 * i) & 31];
            d[0] = make_float4(v.x, v.x, v.y, v.y);
            d[1] = make_float4(v.z, v.z, v.w, v.w);
        }
        if (t < 32) { ssrc[t] = src[base + t]; sdst[t] = dst[base + t]; }
        __syncthreads();

        for (int j0 = 0; j0 < 32; j0 += 2) {
            // hoist the 4 L2 gathers
            float2 xlv0 = xl2[(size_t)ssrc[j0] * HC2 + t];
            float2 xrv0 = xr2[(size_t)sdst[j0] * HC2 + t];
            float2 xlv1 = xl2[(size_t)ssrc[j0 + 1] * HC2 + t];
            float2 xrv1 = xr2[(size_t)sdst[j0 + 1] * HC2 + t];
            ull e0a = 0ull, e0b = 0ull, e1a = 0ull, e1b = 0ull;
            const f4u* ev0 = (const f4u*)sea[j0];
            const f4u* ev1 = (const f4u*)sea[j0 + 1];
            #pragma unroll
            for (int kk = 0; kk < 8; kk++) {
                f4u v0 = ev0[2 * kk], v0b = ev0[2 * kk + 1];
                f4u v1 = ev1[2 * kk], v1b = ev1[2 * kk + 1];
                e0a = fma2(v0.u[0],  w2[4 * kk + 0], e0a);
                e0b = fma2(v0.u[1],  w2[4 * kk + 1], e0b);
                e1a = fma2(v1.u[0],  w2[4 * kk + 0], e1a);
                e1b = fma2(v1.u[1],  w2[4 * kk + 1], e1b);
                e0a = fma2(v0b.u[0], w2[4 * kk + 2], e0a);
                e0b = fma2(v0b.u[1], w2[4 * kk + 3], e0b);
                e1a = fma2(v1b.u[0], w2[4 * kk + 2], e1a);
                e1b = fma2(v1b.u[1], w2[4 * kk + 3], e1b);
            }
            float a0, b0, a1, b1, c0, d0, c1, d1;
            upk2(e0a, a0, b0); upk2(e0b, a1, b1);
            upk2(e1a, c0, d0); upk2(e1b, c1, d1);
            float s0lo = xlv0.x + xrv0.x + a0 + a1;
            float s0hi = xlv0.y + xrv0.y + b0 + b1;
            float s1lo = xlv1.x + xrv1.x + c0 + c1;
            float s1hi = xlv1.y + xrv1.y + d0 + d1;
            s0lo = fmaxf(s0lo, 0.f) + 0.2f * fminf(s0lo, 0.f);
            s0hi = fmaxf(s0hi, 0.f) + 0.2f * fminf(s0hi, 0.f);
            s1lo = fmaxf(s1lo, 0.f) + 0.2f * fminf(s1lo, 0.f);
            s1hi = fmaxf(s1hi, 0.f) + 0.2f * fminf(s1hi, 0.f);
            float p0 = s0lo * attlo + s0hi * atthi;
            float p1 = s1lo * attlo + s1hi * atthi;
            #pragma unroll
            for (int off = 16; off; off >>= 1) {
                p0 += __shfl_down_sync(0xffffffffu, p0, off);
                p1 += __shfl_down_sync(0xffffffffu, p1, off);
            }
            if (lane == 0) {
                wout[(base + j0) * H + wid]     = __expf(p0);
                wout[(base + j0 + 1) * H + wid] = __expf(p1);
            }
        }
        __syncthreads();
    }
}

// ---------------- per-dst normalize + weighted aggregation ----------------
template<int HC, int H, bool RELU>
__global__ void __launch_bounds__(HC / 2) agg3(
    const float* __restrict__ xl, const float* __restrict__ wexp,
    const int* __restrict__ src, const float* __restrict__ bias,
    float* __restrict__ out)
{
    const int n = blockIdx.x, t = threadIdx.x;
    const int lane = t & 31, wid = t >> 5;
    __shared__ float s_w[H][64];
    __shared__ int s_srcn[64];
    __shared__ float s_den[H];
    const int r0 = g_rowptr[n], deg = g_rowptr[n + 1] - r0;
    const float2* xl2 = (const float2*)xl;
    const int HC2 = HC / 2;

    float accx = 0.f, accy = 0.f, dpart = 0.f;
    for (int b0 = 0; b0 < deg; b0 += 64) {
        int cnt = min(64, deg - b0);
        for (int i = lane; i < cnt; i += 32) {
            int e = g_eid[r0 + b0 + i];
            float w = wexp[(size_t)e * H + wid];
            s_w[wid][i] = w;
            dpart += w;
            if (wid == 0) s_srcn[i] = src[e];
        }
        __syncthreads();
        int i = 0;
        for (; i + 4 <= cnt; i += 4) {
            int n0 = s_srcn[i], n1 = s_srcn[i + 1], n2 = s_srcn[i + 2], n3 = s_srcn[i + 3];
            float w0 = s_w[wid][i], w1 = s_w[wid][i + 1], w2v = s_w[wid][i + 2], w3 = s_w[wid][i + 3];
            float2 v0 = xl2[(size_t)n0 * HC2 + t];
            float2 v1 = xl2[(size_t)n1 * HC2 + t];
            float2 v2 = xl2[(size_t)n2 * HC2 + t];
            float2 v3 = xl2[(size_t)n3 * HC2 + t];
            accx += w0 * v0.x + w1 * v1.x + w2v * v2.x + w3 * v3.x;
            accy += w0 * v0.y + w1 * v1.y + w2v * v2.y + w3 * v3.y;
        }
        for (; i < cnt; i++) {
            float w = s_w[wid][i];
            float2 v = xl2[(size_t)s_srcn[i] * HC2 + t];
            accx += w * v.x;
            accy += w * v.y;
        }
        __syncthreads();
    }
    #pragma unroll
    for (int off = 16; off; off >>= 1)
        dpart += __shfl_xor_sync(0xffffffffu, dpart, off);
    if (lane == 0) s_den[wid] = dpart;
    __syncthreads();
    float inv = 1.f / (s_den[wid] + 1e-16f);
    float ox = accx * inv + bias[2 * t];
    float oy = accy * inv + bias[2 * t + 1];
    if (RELU) { ox = fmaxf(ox, 0.f); oy = fmaxf(oy, 0.f); }
    *(float2*)&out[(size_t)n * HC + 2 * t] = make_float2(ox, oy);
}

// ---------------- gate: g_gate[n] = exp(hid[n] . G2w + G2b) ----------------
__global__ void k_gate2(const float* __restrict__ hid, const float* __restrict__ G2w,
                        const float* __restrict__ G2b)
{
    int wid = threadIdx.x >> 5, lane = threadIdx.x & 31;
    int n = blockIdx.x * 4 + wid;
    if (n >= NN) return;
    float v = 0.f;
    #pragma unroll
    for (int i = 0; i < 4; i++) {
        int c = lane + 32 * i;
        v += hid[(size_t)n * 128 + c] * G2w[c];
    }
    #pragma unroll
    for (int off = 16; off; off >>= 1) v += __shfl_xor_sync(0xffffffffu, v, off);
    if (lane == 0) g_gate[n] = __expf(v + G2b[0]);
}

// ---------------- block-per-graph pool + regressor ----------------
__global__ void k_poolout(const int* __restrict__ batch, const float* __restrict__ h3,
                          const float* __restrict__ Wreg, const float* __restrict__ breg,
                          float* __restrict__ out)
{
    const int b = blockIdx.x, c = threadIdx.x;   // 64 threads
    __shared__ int s_range[2];
    if (c < 2) {
        int key = b + c;
        int lo = 0, hi = NN;
        while (lo < hi) { int m = (lo + hi) >> 1; if (batch[m] < key) lo = m + 1; else hi = m; }
        s_range[c] = lo;
    }
    __syncthreads();
    int lo = s_range[0], hi = s_range[1];
    float acc = 0.f, den = 0.f;
    int n = lo;
    for (; n + 4 <= hi; n += 4) {
        float g0 = g_gate[n], g1 = g_gate[n + 1], g2 = g_gate[n + 2], g3 = g_gate[n + 3];
        float h0 = h3[(size_t)n * 64 + c];
        float h1 = h3[(size_t)(n + 1) * 64 + c];
        float h2 = h3[(size_t)(n + 2) * 64 + c];
        float hv3 = h3[(size_t)(n + 3) * 64 + c];
        acc += g0 * h0 + g1 * h1 + g2 * h2 + g3 * hv3;
        den += g0 + g1 + g2 + g3;
    }
    for (; n < hi; n++) {
        float g = g_gate[n];
        acc += g * h3[(size_t)n * 64 + c];
        den += g;
    }
    float v = acc / (den + 1e-16f) * Wreg[c];
    #pragma unroll
    for (int off = 16; off; off >>= 1) v += __shfl_xor_sync(0xffffffffu, v, off);
    __shared__ float sp[2];
    if ((c & 31) == 0) sp[c >> 5] = v;
    __syncthreads();
    if (c == 0) out[b] = sp[0] + sp[1] + breg[0];
}

// ---------------- launch ----------------
extern "C" void kernel_launch(void* const* d_in, const int* in_sizes, int n_in,
                              void* d_out, int out_size)
{
    const float* x     = (const float*)d_in[0];
    const float* eattr = (const float*)d_in[1];
    const int*   eidx  = (const int*)d_in[2];
    const int*   batch = (const int*)d_in[3];
    const float *W1l = (const float*)d_in[4],  *b1l = (const float*)d_in[5];
    const float *W1r = (const float*)d_in[6],  *b1r = (const float*)d_in[7];
    const float *W1e = (const float*)d_in[8],  *att1 = (const float*)d_in[9];
    const float *bias1 = (const float*)d_in[10];
    const float *W2l = (const float*)d_in[11], *b2l = (const float*)d_in[12];
    const float *W2r = (const float*)d_in[13], *b2r = (const float*)d_in[14];
    const float *W2e = (const float*)d_in[15], *att2 = (const float*)d_in[16];
    const float *bias2 = (const float*)d_in[17];
    const float *W3l = (const float*)d_in[18], *b3l = (const float*)d_in[19];
    const float *W3r = (const float*)d_in[20], *b3r = (const float*)d_in[21];
    const float *W3e = (const float*)d_in[22], *att3 = (const float*)d_in[23];
    const float *bias3 = (const float*)d_in[24];
    const float *G1w = (const float*)d_in[25], *G1b = (const float*)d_in[26];
    const float *G2w = (const float*)d_in[27], *G2b = (const float*)d_in[28];
    const float *Wreg = (const float*)d_in[29], *breg = (const float*)d_in[30];
    float* out = (float*)d_out;

    const int* src = eidx;
    const int* dst = eidx + NE;

    float *xl, *xr, *hbuf, *wexp;
    cudaGetSymbolAddress((void**)&xl, g_xl);
    cudaGetSymbolAddress((void**)&xr, g_xr);
    cudaGetSymbolAddress((void**)&hbuf, g_h);
    cudaGetSymbolAddress((void**)&wexp, g_w);

    dim3 g2(2, NN / 64), g1(1, NN / 64);

    // ordering note: app-kernel index 3 (edge_logits3) is what ncu -s 5 profiles
    k_init<<<(NN + 255) / 256, 256>>>();                                          // 0
    sgemm_dual<<<g2, 128>>>(x, W1l, b1l, xl, W1r, b1r, xr, NN, 128, 128);         // 1
    k_count<<<(NE + 255) / 256, 256>>>(dst);                                      // 2
    edge_logits3<128, 2><<<NE / 128, 64>>>(xl, xr, W1e, att1, eattr, src, dst, wexp); // 3
    k_scan<<<1, 1024>>>();                                                        // 4
    k_scatter<<<(NE + 255) / 256, 256>>>(dst);                                    // 5
    agg3<128, 2, true><<<NN, 64>>>(xl, wexp, src, bias1, hbuf);                   // 6

    sgemm_dual<<<g2, 128>>>(hbuf, W2l, b2l, xl, W2r, b2r, xr, NN, 128, 128);      // 7
    edge_logits3<128, 2><<<NE / 128, 64>>>(xl, xr, W2e, att2, eattr, src, dst, wexp); // 8
    agg3<128, 2, true><<<NN, 64>>>(xl, wexp, src, bias2, hbuf);                   // 9

    sgemm_dual<<<g1, 128>>>(hbuf, W3l, b3l, xl, W3r, b3r, xr, NN, 64, 128);       // 10
    edge_logits3<64, 1><<<NE / 128, 32>>>(xl, xr, W3e, att3, eattr, src, dst, wexp);  // 11
    agg3<64, 1, false><<<NN, 32>>>(xl, wexp, src, bias3, hbuf);                   // 12

    sgemm2<<<g2, 128>>>(hbuf, G1w, G1b, xl, NN, 128, 64, 1);                      // 13
    k_gate2<<<NN / 4, 128>>>(xl, G2w, G2b);                                       // 14
    k_poolout<<<NBATCH, 64>>>(batch, hbuf, Wreg, breg, out);                      // 15
}

// round 6
// speedup vs baseline: 1.4009x; 1.2269x over previous
#include <cuda_runtime.h>

#define NN 40000
#define NE 640000
#define NBATCH 64

typedef unsigned long long ull;

// ---------------- f32x2 helpers ----------------
__device__ __forceinline__ ull pk2(float lo, float hi) {
    ull r; asm("mov.b64 %0, {%1,%2};" : "=l"(r) : "f"(lo), "f"(hi)); return r;
}
__device__ __forceinline__ void upk2(ull v, float& lo, float& hi) {
    asm("mov.b64 {%0,%1}, %2;" : "=f"(lo), "=f"(hi) : "l"(v));
}
__device__ __forceinline__ ull fma2(ull a, ull b, ull c) {
    ull d; asm("fma.rn.f32x2 %0, %1, %2, %3;" : "=l"(d) : "l"(a), "l"(b), "l"(c)); return d;
}
union f4u { float4 f; ull u[2]; };
union f2u { float2 f; ull u; };

// ---------------- scratch ----------------
__device__ float g_xl[NN * 128];
__device__ float g_xr[NN * 128];
__device__ float g_h [NN * 128];
__device__ float g_w  [NE * 2];       // exp(logit)
__device__ int   g_rowptr[NN + 1];
__device__ int   g_cursor[NN];
__device__ int   g_eid[NE];
__device__ float g_gate[NN];          // exp(gate logit)

// ---------------- CSR build ----------------
__global__ void k_init() {
    int i = blockIdx.x * blockDim.x + threadIdx.x;
    if (i < NN) g_cursor[i] = 0;
}
__global__ void k_count(const int* __restrict__ dst) {
    int e = blockIdx.x * blockDim.x + threadIdx.x;
    if (e < NE) atomicAdd(&g_cursor[dst[e]], 1);
}
// single-block scan: writes rowptr AND resets cursor to row start
__global__ void k_scan() {
    __shared__ int s[2][1024];
    __shared__ int base_s;
    int tid = threadIdx.x;
    if (tid == 0) { base_s = 0; g_rowptr[0] = 0; }
    __syncthreads();
    for (int chunk = 0; chunk * 1024 < NN; chunk++) {
        int i = chunk * 1024 + tid;
        int v = (i < NN) ? g_cursor[i] : 0;
        int buf = 0;
        s[0][tid] = v;
        __syncthreads();
        #pragma unroll
        for (int off = 1; off < 1024; off <<= 1) {
            int t = s[buf][tid];
            if (tid >= off) t += s[buf][tid - off];
            s[1 - buf][tid] = t;
            buf ^= 1;
            __syncthreads();
        }
        int incl = s[buf][tid];
        int b = base_s;
        if (i < NN) {
            g_rowptr[i + 1] = b + incl;
            g_cursor[i] = b + incl - v;
        }
        __syncthreads();
        if (tid == 1023) base_s = b + incl;
        __syncthreads();
    }
}
__global__ void k_scatter(const int* __restrict__ dst) {
    int e = blockIdx.x * blockDim.x + threadIdx.x;
    if (e < NE) {
        int p = atomicAdd(&g_cursor[dst[e]], 1);
        g_eid[p] = e;
    }
}

// ---------------- dual f32x2 GEMM ----------------
__global__ void __launch_bounds__(128, 4) sgemm_dual(
    const float* __restrict__ A,
    const float* __restrict__ Bl, const float* __restrict__ bil, float* __restrict__ Cl,
    const float* __restrict__ Br, const float* __restrict__ bir, float* __restrict__ Cr,
    int M, int N, int K)
{
    __shared__ float2 sA[16][64];
    __shared__ float  sBl[16][64];
    __shared__ float  sBr[16][64];
    const int tid = threadIdx.x;
    const int bm = blockIdx.y * 64, bn = blockIdx.x * 64;
    const int tx = tid & 7, ty = tid >> 3;
    const int ar = tid >> 1, ak = (tid & 1) * 8;
    const int br = tid >> 3, bc = (tid & 7) * 8;

    ull accl[4][4], accr[4][4];
    #pragma unroll
    for (int i = 0; i < 4; i++)
        #pragma unroll
        for (int j = 0; j < 4; j++) { accl[i][j] = 0ull; accr[i][j] = 0ull; }

    for (int k0 = 0; k0 < K; k0 += 16) {
        float4 a0 = *(const float4*)&A[(size_t)(bm + ar) * K + k0 + ak];
        float4 a1 = *(const float4*)&A[(size_t)(bm + ar) * K + k0 + ak + 4];
        sA[ak + 0][ar] = make_float2(a0.x, a0.x);
        sA[ak + 1][ar] = make_float2(a0.y, a0.y);
        sA[ak + 2][ar] = make_float2(a0.z, a0.z);
        sA[ak + 3][ar] = make_float2(a0.w, a0.w);
        sA[ak + 4][ar] = make_float2(a1.x, a1.x);
        sA[ak + 5][ar] = make_float2(a1.y, a1.y);
        sA[ak + 6][ar] = make_float2(a1.z, a1.z);
        sA[ak + 7][ar] = make_float2(a1.w, a1.w);
        *(float4*)&sBl[br][bc]     = *(const float4*)&Bl[(size_t)(k0 + br) * N + bn + bc];
        *(float4*)&sBl[br][bc + 4] = *(const float4*)&Bl[(size_t)(k0 + br) * N + bn + bc + 4];
        *(float4*)&sBr[br][bc]     = *(const float4*)&Br[(size_t)(k0 + br) * N + bn + bc];
        *(float4*)&sBr[br][bc + 4] = *(const float4*)&Br[(size_t)(k0 + br) * N + bn + bc + 4];
        __syncthreads();
        #pragma unroll
        for (int k = 0; k < 16; k++) {
            f4u a01 = *(f4u*)&sA[k][ty * 4];
            f4u a23 = *(f4u*)&sA[k][ty * 4 + 2];
            f4u bl01 = *(f4u*)&sBl[k][tx * 8];
            f4u bl23 = *(f4u*)&sBl[k][tx * 8 + 4];
            f4u br01 = *(f4u*)&sBr[k][tx * 8];
            f4u br23 = *(f4u*)&sBr[k][tx * 8 + 4];
            ull av[4] = {a01.u[0], a01.u[1], a23.u[0], a23.u[1]};
            ull blv[4] = {bl01.u[0], bl01.u[1], bl23.u[0], bl23.u[1]};
            ull brv[4] = {br01.u[0], br01.u[1], br23.u[0], br23.u[1]};
            #pragma unroll
            for (int i = 0; i < 4; i++)
                #pragma unroll
                for (int j = 0; j < 4; j++) {
                    accl[i][j] = fma2(av[i], blv[j], accl[i][j]);
                    accr[i][j] = fma2(av[i], brv[j], accr[i][j]);
                }
        }
        __syncthreads();
    }
    float bsl[8], bsr[8];
    #pragma unroll
    for (int j = 0; j < 8; j++) { bsl[j] = bil[bn + tx * 8 + j]; bsr[j] = bir[bn + tx * 8 + j]; }
    #pragma unroll
    for (int i = 0; i < 4; i++) {
        float ol[8], orr[8];
        #pragma unroll
        for (int j = 0; j < 4; j++) {
            upk2(accl[i][j], ol[2 * j], ol[2 * j + 1]);
            upk2(accr[i][j], orr[2 * j], orr[2 * j + 1]);
        }
        #pragma unroll
        for (int j = 0; j < 8; j++) { ol[j] += bsl[j]; orr[j] += bsr[j]; }
        size_t row = (size_t)(bm + ty * 4 + i);
        *(float4*)&Cl[row * N + bn + tx * 8]     = make_float4(ol[0], ol[1], ol[2], ol[3]);
        *(float4*)&Cl[row * N + bn + tx * 8 + 4] = make_float4(ol[4], ol[5], ol[6], ol[7]);
        *(float4*)&Cr[row * N + bn + tx * 8]     = make_float4(orr[0], orr[1], orr[2], orr[3]);
        *(float4*)&Cr[row * N + bn + tx * 8 + 4] = make_float4(orr[4], orr[5], orr[6], orr[7]);
    }
}

// ---------------- single GEMM (gate layer, relu) ----------------
__global__ void __launch_bounds__(128) sgemm2(
    const float* __restrict__ A, const float* __restrict__ B,
    const float* __restrict__ bias, float* __restrict__ C,
    int M, int N, int K, int doRelu)
{
    __shared__ float2 sA[16][64];
    __shared__ float  sB[16][64];
    const int tid = threadIdx.x;
    const int bm = blockIdx.y * 64, bn = blockIdx.x * 64;
    const int tx = tid & 7, ty = tid >> 3;
    const int ar = tid >> 1, ak = (tid & 1) * 8;
    const int br = tid >> 3, bc = (tid & 7) * 8;

    ull acc[4][4];
    #pragma unroll
    for (int i = 0; i < 4; i++)
        #pragma unroll
        for (int j = 0; j < 4; j++) acc[i][j] = 0ull;

    for (int k0 = 0; k0 < K; k0 += 16) {
        float4 a0 = *(const float4*)&A[(size_t)(bm + ar) * K + k0 + ak];
        float4 a1 = *(const float4*)&A[(size_t)(bm + ar) * K + k0 + ak + 4];
        sA[ak + 0][ar] = make_float2(a0.x, a0.x);
        sA[ak + 1][ar] = make_float2(a0.y, a0.y);
        sA[ak + 2][ar] = make_float2(a0.z, a0.z);
        sA[ak + 3][ar] = make_float2(a0.w, a0.w);
        sA[ak + 4][ar] = make_float2(a1.x, a1.x);
        sA[ak + 5][ar] = make_float2(a1.y, a1.y);
        sA[ak + 6][ar] = make_float2(a1.z, a1.z);
        sA[ak + 7][ar] = make_float2(a1.w, a1.w);
        *(float4*)&sB[br][bc]     = *(const float4*)&B[(size_t)(k0 + br) * N + bn + bc];
        *(float4*)&sB[br][bc + 4] = *(const float4*)&B[(size_t)(k0 + br) * N + bn + bc + 4];
        __syncthreads();
        #pragma unroll
        for (int k = 0; k < 16; k++) {
            f4u a01 = *(f4u*)&sA[k][ty * 4];
            f4u a23 = *(f4u*)&sA[k][ty * 4 + 2];
            f4u b01 = *(f4u*)&sB[k][tx * 8];
            f4u b23 = *(f4u*)&sB[k][tx * 8 + 4];
            ull av[4] = {a01.u[0], a01.u[1], a23.u[0], a23.u[1]};
            ull bv[4] = {b01.u[0], b01.u[1], b23.u[0], b23.u[1]};
            #pragma unroll
            for (int i = 0; i < 4; i++)
                #pragma unroll
                for (int j = 0; j < 4; j++)
                    acc[i][j] = fma2(av[i], bv[j], acc[i][j]);
        }
        __syncthreads();
    }
    float bs[8];
    #pragma unroll
    for (int j = 0; j < 8; j++) bs[j] = bias[bn + tx * 8 + j];
    #pragma unroll
    for (int i = 0; i < 4; i++) {
        float o[8];
        #pragma unroll
        for (int j = 0; j < 4; j++) upk2(acc[i][j], o[2 * j], o[2 * j + 1]);
        #pragma unroll
        for (int j = 0; j < 8; j++) {
            o[j] += bs[j];
            if (doRelu) o[j] = fmaxf(o[j], 0.f);
        }
        size_t row = (size_t)(bm + ty * 4 + i);
        *(float4*)&C[row * N + bn + tx * 8]     = make_float4(o[0], o[1], o[2], o[3]);
        *(float4*)&C[row * N + bn + tx * 8 + 4] = make_float4(o[4], o[5], o[6], o[7]);
    }
}

// ---------------- edge weights v4: one warp per edge batch, all channels ----------
// w[e,h] = exp(att_h . lrelu(xl[src]+xr[dst]+ea@We))
// Block: 256 threads (8 warps), 128 edges. Each warp handles 16 edges (2 batches
// of 8), covering ALL HC channels (CPT = HC/32 channels per thread).
// ea staged TRANSPOSED in smem: one broadcast LDS.128 = 4 edges' ea at one k.
template<int HC, int H>
__global__ void __launch_bounds__(256) edge_logits4(
    const float* __restrict__ xl, const float* __restrict__ xr,
    const float* __restrict__ We, const float* __restrict__ att,
    const float* __restrict__ ea, const int* __restrict__ src,
    const int* __restrict__ dst, float* __restrict__ wout)
{
    constexpr int CPT = HC / 32;      // 4 or 2 channels per thread
    constexpr int CP  = CPT / 2;      // f32x2 pairs per thread
    constexpr int EPB = 128;
    const int tid = threadIdx.x;
    const int wid = tid >> 5, lane = tid & 31;
    const long ebase = (long)blockIdx.x * EPB;

    __shared__ float sWe[32][HC];
    __shared__ float sea_t[32][EPB];
    __shared__ int ssrc[EPB], sdst[EPB];

    // stage We [32][HC]
    for (int i = tid * 4; i < 32 * HC; i += 256 * 4)
        *(float4*)&sWe[0][i] = *(const float4*)&We[i];
    // stage ea transposed + indices (threads 0..127, one edge each)
    if (tid < EPB) {
        const float4* er = (const float4*)(ea + (ebase + tid) * 32);
        #pragma unroll
        for (int q = 0; q < 8; q++) {
            float4 v = er[q];
            sea_t[q * 4 + 0][tid] = v.x;
            sea_t[q * 4 + 1][tid] = v.y;
            sea_t[q * 4 + 2][tid] = v.z;
            sea_t[q * 4 + 3][tid] = v.w;
        }
        ssrc[tid] = src[ebase + tid];
        sdst[tid] = dst[ebase + tid];
    }
    // att for this thread's channels
    float atr[CPT];
    #pragma unroll
    for (int i = 0; i < CPT; i++) atr[i] = att[lane * CPT + i];
    __syncthreads();

    #pragma unroll
    for (int eb = 0; eb < 2; eb++) {
        const int e0 = wid * 16 + eb * 8;   // local edge base (8 edges)
        ull acc[8][CP];
        #pragma unroll
        for (int e = 0; e < 8; e++)
            #pragma unroll
            for (int p = 0; p < CP; p++) acc[e][p] = 0ull;

        #pragma unroll 4
        for (int k = 0; k < 32; k++) {
            // We pairs for this thread's channels (natural adjacent pairs)
            ull wv[CP];
            if (CPT == 4) {
                f4u w4; w4.f = *(float4*)&sWe[k][lane * 4];
                wv[0] = w4.u[0]; if (CP > 1) wv[1] = w4.u[1];
            } else {
                f2u w2; w2.f = *(float2*)&sWe[k][lane * 2];
                wv[0] = w2.u;
            }
            // 8 edges' ea at k (broadcast)
            float4 ev0 = *(float4*)&sea_t[k][e0];
            float4 ev1 = *(float4*)&sea_t[k][e0 + 4];
            ull d[8];
            d[0] = pk2(ev0.x, ev0.x); d[1] = pk2(ev0.y, ev0.y);
            d[2] = pk2(ev0.z, ev0.z); d[3] = pk2(ev0.w, ev0.w);
            d[4] = pk2(ev1.x, ev1.x); d[5] = pk2(ev1.y, ev1.y);
            d[6] = pk2(ev1.z, ev1.z); d[7] = pk2(ev1.w, ev1.w);
            #pragma unroll
            for (int e = 0; e < 8; e++)
                #pragma unroll
                for (int p = 0; p < CP; p++)
                    acc[e][p] = fma2(d[e], wv[p], acc[e][p]);
        }

        // epilogue: gather xl/xr, lrelu, att-dot, per-head reduce, exp, store
        #pragma unroll
        for (int e = 0; e < 8; e++) {
            const size_t sn = (size_t)ssrc[e0 + e];
            const size_t dn = (size_t)sdst[e0 + e];
            float s[CPT];
            if (CPT == 4) {
                float4 xa = *(const float4*)&xl[sn * HC + lane * 4];
                float4 xb = *(const float4*)&xr[dn * HC + lane * 4];
                float e01lo, e01hi, e23lo, e23hi;
                upk2(acc[e][0], e01lo, e01hi);
                upk2(acc[e][1], e23lo, e23hi);
                s[0] = xa.x + xb.x + e01lo;
                s[1] = xa.y + xb.y + e01hi;
                s[2] = xa.z + xb.z + e23lo;
                s[3] = xa.w + xb.w + e23hi;
            } else {
                float2 xa = *(const float2*)&xl[sn * HC + lane * 2];
                float2 xb = *(const float2*)&xr[dn * HC + lane * 2];
                float elo, ehi;
                upk2(acc[e][0], elo, ehi);
                s[0] = xa.x + xb.x + elo;
                s[1] = xa.y + xb.y + ehi;
            }
            float p = 0.f;
            #pragma unroll
            for (int i = 0; i < CPT; i++) {
                float v = fmaxf(s[i], 0.f) + 0.2f * fminf(s[i], 0.f);
                p += v * atr[i];
            }
            const long ge = ebase + e0 + e;
            if (H == 2) {
                // head 0 = lanes 0-15, head 1 = lanes 16-31
                #pragma unroll
                for (int off = 8; off; off >>= 1)
                    p += __shfl_down_sync(0xffffffffu, p, off, 16);
                if ((lane & 15) == 0) wout[ge * 2 + (lane >> 4)] = __expf(p);
            } else {
                #pragma unroll
                for (int off = 16; off; off >>= 1)
                    p += __shfl_down_sync(0xffffffffu, p, off);
                if (lane == 0) wout[ge] = __expf(p);
            }
        }
    }
}

// ---------------- per-dst normalize + weighted aggregation ----------------
template<int HC, int H, bool RELU>
__global__ void __launch_bounds__(HC / 2) agg3(
    const float* __restrict__ xl, const float* __restrict__ wexp,
    const int* __restrict__ src, const float* __restrict__ bias,
    float* __restrict__ out)
{
    const int n = blockIdx.x, t = threadIdx.x;
    const int lane = t & 31, wid = t >> 5;
    __shared__ float s_w[H][64];
    __shared__ int s_srcn[64];
    __shared__ float s_den[H];
    const int r0 = g_rowptr[n], deg = g_rowptr[n + 1] - r0;
    const float2* xl2 = (const float2*)xl;
    const int HC2 = HC / 2;

    float accx = 0.f, accy = 0.f, dpart = 0.f;
    for (int b0 = 0; b0 < deg; b0 += 64) {
        int cnt = min(64, deg - b0);
        for (int i = lane; i < cnt; i += 32) {
            int e = g_eid[r0 + b0 + i];
            float w = wexp[(size_t)e * H + wid];
            s_w[wid][i] = w;
            dpart += w;
            if (wid == 0) s_srcn[i] = src[e];
        }
        __syncthreads();
        int i = 0;
        for (; i + 4 <= cnt; i += 4) {
            int n0 = s_srcn[i], n1 = s_srcn[i + 1], n2 = s_srcn[i + 2], n3 = s_srcn[i + 3];
            float w0 = s_w[wid][i], w1 = s_w[wid][i + 1], w2v = s_w[wid][i + 2], w3 = s_w[wid][i + 3];
            float2 v0 = xl2[(size_t)n0 * HC2 + t];
            float2 v1 = xl2[(size_t)n1 * HC2 + t];
            float2 v2 = xl2[(size_t)n2 * HC2 + t];
            float2 v3 = xl2[(size_t)n3 * HC2 + t];
            accx += w0 * v0.x + w1 * v1.x + w2v * v2.x + w3 * v3.x;
            accy += w0 * v0.y + w1 * v1.y + w2v * v2.y + w3 * v3.y;
        }
        for (; i < cnt; i++) {
            float w = s_w[wid][i];
            float2 v = xl2[(size_t)s_srcn[i] * HC2 + t];
            accx += w * v.x;
            accy += w * v.y;
        }
        __syncthreads();
    }
    #pragma unroll
    for (int off = 16; off; off >>= 1)
        dpart += __shfl_xor_sync(0xffffffffu, dpart, off);
    if (lane == 0) s_den[wid] = dpart;
    __syncthreads();
    float inv = 1.f / (s_den[wid] + 1e-16f);
    float ox = accx * inv + bias[2 * t];
    float oy = accy * inv + bias[2 * t + 1];
    if (RELU) { ox = fmaxf(ox, 0.f); oy = fmaxf(oy, 0.f); }
    *(float2*)&out[(size_t)n * HC + 2 * t] = make_float2(ox, oy);
}

// ---------------- gate: g_gate[n] = exp(hid[n] . G2w + G2b) ----------------
__global__ void k_gate2(const float* __restrict__ hid, const float* __restrict__ G2w,
                        const float* __restrict__ G2b)
{
    int wid = threadIdx.x >> 5, lane = threadIdx.x & 31;
    int n = blockIdx.x * 4 + wid;
    if (n >= NN) return;
    float v = 0.f;
    #pragma unroll
    for (int i = 0; i < 4; i++) {
        int c = lane + 32 * i;
        v += hid[(size_t)n * 128 + c] * G2w[c];
    }
    #pragma unroll
    for (int off = 16; off; off >>= 1) v += __shfl_xor_sync(0xffffffffu, v, off);
    if (lane == 0) g_gate[n] = __expf(v + G2b[0]);
}

// ---------------- block-per-graph pool + regressor ----------------
__global__ void k_poolout(const int* __restrict__ batch, const float* __restrict__ h3,
                          const float* __restrict__ Wreg, const float* __restrict__ breg,
                          float* __restrict__ out)
{
    const int b = blockIdx.x, c = threadIdx.x;   // 64 threads
    __shared__ int s_range[2];
    if (c < 2) {
        int key = b + c;
        int lo = 0, hi = NN;
        while (lo < hi) { int m = (lo + hi) >> 1; if (batch[m] < key) lo = m + 1; else hi = m; }
        s_range[c] = lo;
    }
    __syncthreads();
    int lo = s_range[0], hi = s_range[1];
    float acc = 0.f, den = 0.f;
    int n = lo;
    for (; n + 4 <= hi; n += 4) {
        float g0 = g_gate[n], g1 = g_gate[n + 1], g2 = g_gate[n + 2], g3 = g_gate[n + 3];
        float h0 = h3[(size_t)n * 64 + c];
        float h1 = h3[(size_t)(n + 1) * 64 + c];
        float h2 = h3[(size_t)(n + 2) * 64 + c];
        float hv3 = h3[(size_t)(n + 3) * 64 + c];
        acc += g0 * h0 + g1 * h1 + g2 * h2 + g3 * hv3;
        den += g0 + g1 + g2 + g3;
    }
    for (; n < hi; n++) {
        float g = g_gate[n];
        acc += g * h3[(size_t)n * 64 + c];
        den += g;
    }
    float v = acc / (den + 1e-16f) * Wreg[c];
    #pragma unroll
    for (int off = 16; off; off >>= 1) v += __shfl_xor_sync(0xffffffffu, v, off);
    __shared__ float sp[2];
    if ((c & 31) == 0) sp[c >> 5] = v;
    __syncthreads();
    if (c == 0) out[b] = sp[0] + sp[1] + breg[0];
}

// ---------------- launch ----------------
extern "C" void kernel_launch(void* const* d_in, const int* in_sizes, int n_in,
                              void* d_out, int out_size)
{
    const float* x     = (const float*)d_in[0];
    const float* eattr = (const float*)d_in[1];
    const int*   eidx  = (const int*)d_in[2];
    const int*   batch = (const int*)d_in[3];
    const float *W1l = (const float*)d_in[4],  *b1l = (const float*)d_in[5];
    const float *W1r = (const float*)d_in[6],  *b1r = (const float*)d_in[7];
    const float *W1e = (const float*)d_in[8],  *att1 = (const float*)d_in[9];
    const float *bias1 = (const float*)d_in[10];
    const float *W2l = (const float*)d_in[11], *b2l = (const float*)d_in[12];
    const float *W2r = (const float*)d_in[13], *b2r = (const float*)d_in[14];
    const float *W2e = (const float*)d_in[15], *att2 = (const float*)d_in[16];
    const float *bias2 = (const float*)d_in[17];
    const float *W3l = (const float*)d_in[18], *b3l = (const float*)d_in[19];
    const float *W3r = (const float*)d_in[20], *b3r = (const float*)d_in[21];
    const float *W3e = (const float*)d_in[22], *att3 = (const float*)d_in[23];
    const float *bias3 = (const float*)d_in[24];
    const float *G1w = (const float*)d_in[25], *G1b = (const float*)d_in[26];
    const float *G2w = (const float*)d_in[27], *G2b = (const float*)d_in[28];
    const float *Wreg = (const float*)d_in[29], *breg = (const float*)d_in[30];
    float* out = (float*)d_out;

    const int* src = eidx;
    const int* dst = eidx + NE;

    float *xl, *xr, *hbuf, *wexp;
    cudaGetSymbolAddress((void**)&xl, g_xl);
    cudaGetSymbolAddress((void**)&xr, g_xr);
    cudaGetSymbolAddress((void**)&hbuf, g_h);
    cudaGetSymbolAddress((void**)&wexp, g_w);

    dim3 g2(2, NN / 64), g1(1, NN / 64);

    // ordering note: app-kernel index 3 (edge_logits4) is what ncu -s 5 profiles
    k_init<<<(NN + 255) / 256, 256>>>();                                          // 0
    sgemm_dual<<<g2, 128>>>(x, W1l, b1l, xl, W1r, b1r, xr, NN, 128, 128);         // 1
    k_count<<<(NE + 255) / 256, 256>>>(dst);                                      // 2
    edge_logits4<128, 2><<<NE / 128, 256>>>(xl, xr, W1e, att1, eattr, src, dst, wexp); // 3
    k_scan<<<1, 1024>>>();                                                        // 4
    k_scatter<<<(NE + 255) / 256, 256>>>(dst);                                    // 5
    agg3<128, 2, true><<<NN, 64>>>(xl, wexp, src, bias1, hbuf);                   // 6

    sgemm_dual<<<g2, 128>>>(hbuf, W2l, b2l, xl, W2r, b2r, xr, NN, 128, 128);      // 7
    edge_logits4<128, 2><<<NE / 128, 256>>>(xl, xr, W2e, att2, eattr, src, dst, wexp); // 8
    agg3<128, 2, true><<<NN, 64>>>(xl, wexp, src, bias2, hbuf);                   // 9

    sgemm_dual<<<g1, 128>>>(hbuf, W3l, b3l, xl, W3r, b3r, xr, NN, 64, 128);       // 10
    edge_logits4<64, 1><<<NE / 128, 256>>>(xl, xr, W3e, att3, eattr, src, dst, wexp);  // 11
    agg3<64, 1, false><<<NN, 32>>>(xl, wexp, src, bias3, hbuf);                   // 12

    sgemm2<<<g2, 128>>>(hbuf, G1w, G1b, xl, NN, 128, 64, 1);                      // 13
    k_gate2<<<NN / 4, 128>>>(xl, G2w, G2b);                                       // 14
    k_poolout<<<NBATCH, 64>>>(batch, hbuf, Wreg, breg, out);                      // 15
}